// round 11
// baseline (speedup 1.0000x reference)
#include <cuda_runtime.h>
#include <cuda_bf16.h>
#include <cstdint>

// BitLevelMapper: B=4194304 rows x 16 bits.
// bits:   [B,16] int32 {0,1}  (d_in[0])
// tables: [16, 32768] float32 {0,1} (d_in[1])
// out:    [B,16] float32
//
// R11: single fused kernel. Grid = 1216 CTAs = exactly one resident wave
// (__launch_bounds__(256,8): <=32 regs, 8.2KB smem -> 8 CTAs/SM guaranteed),
// so a software grid barrier is deadlock-free. First 2052 global warps do
// the ballot pack; all CTAs cross a monotonic ticket barrier (epoch =
// ticket/gridDim, no reset needed across graph replays); then the verified
// R9 map body runs. Removes the second launch + inter-kernel gap (~7us).

#define NBITS   16
#define TSIZE   32768           // 2^15 entries per table row
#define NWORDS  2052            // sum over i of ceil(max(2^i,32)/32)

__device__ uint32_t g_packed[NWORDS];
__device__ unsigned g_arrive = 0;    // monotonic ticket counter (never reset)

// word offset of table row i in the packed layout
__host__ __device__ __forceinline__ int tab_off(int i) {
    return (i < 5) ? i : ((1 << (i - 5)) + 4);
}

#define MAP_BLOCKS  1216        // 152 SMs x 8 CTAs: one full resident wave
#define MAP_THREADS 256

__global__ void __launch_bounds__(MAP_THREADS, 8)
fused_kernel(const float* __restrict__ tables,
             const int4* __restrict__ bits4,
             float4* __restrict__ out4, int nquads) {
    // ---- Phase 1: distributed ballot pack (first NWORDS global warps) ----
    {
        int gw   = (blockIdx.x * blockDim.x + threadIdx.x) >> 5;
        int lane = threadIdx.x & 31;
        if (gw < NWORDS) {
            int i = 0;
            #pragma unroll
            for (int r = 1; r < 16; r++)
                if (gw >= tab_off(r)) i = r;
            int lw = gw - tab_off(i);
            float v = tables[(size_t)i * TSIZE + lw * 32 + lane];
            unsigned word = __ballot_sync(0xffffffffu, v != 0.0f);
            if (lane == 0) g_packed[gw] = word;
        }
    }

    // ---- Grid barrier: monotonic ticket, replay-safe, no reset ----
    __threadfence();                      // release g_packed writes
    __syncthreads();                      // whole CTA done with its pack part
    __shared__ unsigned s_go;
    if (threadIdx.x == 0) {
        unsigned ticket = atomicAdd(&g_arrive, 1u);
        unsigned target = (ticket / (unsigned)gridDim.x + 1u) * (unsigned)gridDim.x;
        volatile unsigned* p = &g_arrive;
        while (*p < target) __nanosleep(64);
        s_go = 1;
    }
    __syncthreads();
    __threadfence();                      // acquire g_packed writes
    (void)s_go;

    // ---- Phase 2: stage packed table, then R9 map body ----
    __shared__ uint32_t s_tab[NWORDS];
    for (int t = threadIdx.x; t < NWORDS; t += blockDim.x)
        s_tab[t] = g_packed[t];
    __syncthreads();

    const int stride = gridDim.x * blockDim.x;
    const int base_t = blockIdx.x * blockDim.x + threadIdx.x;
    const int q      = base_t & 3;           // quarter within row (lane-group pos)
    const int shift  = 15 - 4 * q;           // bit position of v.x in pattern P

    const int nmain  = nquads / stride;      // uniform across all threads

    // main loop + one residual iteration; the t<nquads predicate is
    // warp-uniform ((nquads % stride) % 32 == 0) so the shuffle path is safe.
    for (int it = 0; it <= nmain; it++) {
        int t = base_t + it * stride;
        if (t >= nquads) break;              // warp-uniform exit

        int4 v = bits4[t];

        // partial 16-bit pattern: bit j (array order) sits at position 15-j
        unsigned P = ((unsigned)v.x << shift)       | ((unsigned)v.y << (shift - 1))
                   | ((unsigned)v.z << (shift - 2)) | ((unsigned)v.w << (shift - 3));
        // OR-reduce across the aligned 4-lane group -> full pattern in all lanes
        P |= __shfl_xor_sync(0xffffffffu, P, 1);
        P |= __shfl_xor_sync(0xffffffffu, P, 2);

        float o[4];
        #pragma unroll
        for (int m = 0; m < 4; m++) {
            int i = shift - m;                             // table row index
            unsigned addr = P & ((1u << i) - 1u);          // prefix of context
            uint32_t wv = s_tab[tab_off(i) + (addr >> 5)];
            unsigned x = ((wv >> (addr & 31u)) ^ (P >> i)) & 1u;   // bit ^ flip
            o[m] = __uint_as_float((0u - x) & 0x3f800000u);        // x ? 1.0f : 0.0f
        }
        out4[t] = make_float4(o[0], o[1], o[2], o[3]);
    }
}

extern "C" void kernel_launch(void* const* d_in, const int* in_sizes, int n_in,
                              void* d_out, int out_size) {
    const float* tables = (const float*)d_in[1];
    const int4*  bits4  = (const int4*)d_in[0];
    float4*      out4   = (float4*)d_out;

    int nquads = in_sizes[0] / 4;      // 16777216

    fused_kernel<<<MAP_BLOCKS, MAP_THREADS>>>(tables, bits4, out4, nquads);
}

// round 12
// speedup vs baseline: 1.0650x; 1.0650x over previous
#include <cuda_runtime.h>
#include <cuda_bf16.h>
#include <cstdint>

// BitLevelMapper: B=4194304 rows x 16 bits.
// bits:   [B,16] int32 {0,1}  (d_in[0])
// tables: [16, 32768] float32 {0,1} (d_in[1])
// out:    [B,16] float32
//
// R12: best verified composition. PDL two-kernel (overhead floor ~7.2us,
// vs 10.2 plain / 7.6 fused-barrier), R9 map body (81.7us best, at the
// 512MiB mixed-stream DRAM wall), plus: the first bits4 load is issued
// BEFORE cudaGridDependencySynchronize() — it doesn't depend on the pack,
// so the dependency wait overlaps the first DRAM fetch in every CTA.

#define NBITS   16
#define TSIZE   32768           // 2^15 entries per table row
#define NWORDS  2052            // sum over i of ceil(max(2^i,32)/32)

__device__ uint32_t g_packed[NWORDS];

// word offset of table row i in the packed layout
__host__ __device__ __forceinline__ int tab_off(int i) {
    return (i < 5) ? i : ((1 << (i - 5)) + 4);
}

// One warp per packed word: lane b reads entry lw*32+b, ballot packs.
__global__ void pack_tables_kernel(const float* __restrict__ tables) {
    int gw   = (blockIdx.x * blockDim.x + threadIdx.x) >> 5;
    int lane = threadIdx.x & 31;
    if (gw < NWORDS) {
        int i = 0;
        #pragma unroll
        for (int r = 1; r < 16; r++)
            if (gw >= tab_off(r)) i = r;
        int lw = gw - tab_off(i);
        float v = tables[(size_t)i * TSIZE + lw * 32 + lane];
        unsigned word = __ballot_sync(0xffffffffu, v != 0.0f);
        if (lane == 0) g_packed[gw] = word;
    }
    __threadfence();                              // order g_packed before signal
    cudaTriggerProgrammaticLaunchCompletion();    // release dependent launch early
}

#define MAP_BLOCKS  1216        // 152 SMs x 8 CTAs: one full resident wave
#define MAP_THREADS 256

__device__ __forceinline__ float4 quad_out(
    int4 v, int shift, const uint32_t* __restrict__ s_tab)
{
    // partial 16-bit pattern: bit j (array order) sits at position 15-j
    unsigned P = ((unsigned)v.x << shift)       | ((unsigned)v.y << (shift - 1))
               | ((unsigned)v.z << (shift - 2)) | ((unsigned)v.w << (shift - 3));
    // OR-reduce across the aligned 4-lane group -> full pattern in all 4 lanes
    P |= __shfl_xor_sync(0xffffffffu, P, 1);
    P |= __shfl_xor_sync(0xffffffffu, P, 2);

    float o[4];
    #pragma unroll
    for (int m = 0; m < 4; m++) {
        int i = shift - m;                             // table row index
        unsigned addr = P & ((1u << i) - 1u);          // prefix of context
        uint32_t wv = s_tab[tab_off(i) + (addr >> 5)];
        unsigned x = ((wv >> (addr & 31u)) ^ (P >> i)) & 1u;   // bit ^ flip
        o[m] = __uint_as_float((0u - x) & 0x3f800000u);        // x ? 1.0f : 0.0f
    }
    return make_float4(o[0], o[1], o[2], o[3]);
}

__global__ void __launch_bounds__(MAP_THREADS, 8)
map_kernel(const int4* __restrict__ bits4, float4* __restrict__ out4, int nquads) {
    const int stride = gridDim.x * blockDim.x;
    const int base_t = blockIdx.x * blockDim.x + threadIdx.x;
    const int q      = base_t & 3;           // quarter within row (lane-group pos)
    const int shift  = 15 - 4 * q;           // bit position of v.x in pattern P
    const int nmain  = nquads / stride;      // uniform across all threads

    // First input load is independent of the pack — issue it before the
    // dependency sync so the wait overlaps the DRAM fetch.
    int4 v0 = bits4[base_t];                 // base_t < nquads always here

    cudaGridDependencySynchronize();         // g_packed now valid

    __shared__ uint32_t s_tab[NWORDS];
    for (int t = threadIdx.x; t < NWORDS; t += blockDim.x)
        s_tab[t] = g_packed[t];
    __syncthreads();

    // iteration 0 (peeled, uses the pre-sync load)
    out4[base_t] = quad_out(v0, shift, s_tab);

    // iterations 1..nmain; residual predicate is warp-uniform
    // ((nquads % stride) % 32 == 0) so the shuffle path is safe in the tail.
    for (int it = 1; it <= nmain; it++) {
        int t = base_t + it * stride;
        if (t >= nquads) break;              // warp-uniform exit
        int4 v = bits4[t];
        out4[t] = quad_out(v, shift, s_tab);
    }
}

extern "C" void kernel_launch(void* const* d_in, const int* in_sizes, int n_in,
                              void* d_out, int out_size) {
    const int4*  bits4  = (const int4*)d_in[0];
    const float* tables = (const float*)d_in[1];
    float4*      out4   = (float4*)d_out;

    int nquads = in_sizes[0] / 4;      // 16777216

    pack_tables_kernel<<<(NWORDS * 32 + 255) / 256, 256>>>(tables);

    cudaLaunchConfig_t cfg = {};
    cfg.gridDim  = dim3(MAP_BLOCKS, 1, 1);
    cfg.blockDim = dim3(MAP_THREADS, 1, 1);
    cfg.dynamicSmemBytes = 0;
    cfg.stream = 0;                    // legacy default stream (capture target)
    cudaLaunchAttribute attr[1];
    attr[0].id = cudaLaunchAttributeProgrammaticStreamSerialization;
    attr[0].val.programmaticStreamSerializationAllowed = 1;
    cfg.attrs = attr;
    cfg.numAttrs = 1;
    cudaLaunchKernelEx(&cfg, map_kernel, bits4, out4, nquads);
}